// round 6
// baseline (speedup 1.0000x reference)
#include <cuda_runtime.h>
#include <cstdint>

// ---------------- problem constants ----------------
#define HEADS_N 4
#define BSZ 2
#define NTOT 8192        // THW
#define MTOT 1024        // HW
#define CVTOT 512
#define M_T 64           // m-tile per block
#define NSPLIT 4
#define NPS (NTOT / NSPLIT)     // 2048
#define NCH 64                  // n per chunk
#define NCHUNKS (NPS / NCH)     // 32
#define NTHREADS 512

// ---------------- device scratch (no cudaMalloc allowed) ----------------
__device__ __align__(16) float g_partial[NSPLIT * BSZ * CVTOT * MTOT]; // 16 MB
__device__ __align__(16) float g_Kt[BSZ * HEADS_N * NTOT * 32];        // [b][h][n][32k perm] 8 MB
__device__ __align__(16) float g_Q [BSZ * HEADS_N * MTOT * 32];        // [b][h][m][32k perm] 1 MB
__device__ __align__(16) float g_bias[BSZ * HEADS_N * MTOT];           // 32 KB

// ---------------- smem layout (float offsets) ----------------
// bias[4][64] @0 ; msP[64] @256 ; Q[4][64][36] @384 ; Kt[4][64][36] @9600 ;
// SP[4][64][68] @18816 ; mvS[128][68] @36224 ; total 44928 floats = 179712 B
#define F_BIAS 0
#define F_MS   256
#define F_Q    384
#define F_KT   9600
#define F_SP   18816
#define F_MV   36224
#define SM_TOTAL (44928 * 4)

// ---------------- helpers ----------------
__device__ __host__ __forceinline__ int permk(int k) {
    // within-8 order [0,4,1,5,2,6,3,7]: pos = 2*(k%4) + (k%8)/4
    return (k & ~7) | ((k & 3) << 1) | ((k & 7) >> 2);
}
__device__ __forceinline__ float rn_tf32(float x) {
    uint32_t u;
    asm("cvt.rna.tf32.f32 %0, %1;" : "=r"(u) : "f"(x));
    return __uint_as_float(u);
}
__device__ __forceinline__ void mma_tf32(float* d, float2 aa, float2 ab, float2 bb) {
    // fragment: a0=(rowg,k=t) a1=(rowg+8,k=t) a2=(rowg,k=t+4) a3=(rowg+8,k=t+4)
    asm volatile(
        "mma.sync.aligned.m16n8k8.row.col.f32.tf32.tf32.f32 "
        "{%0,%1,%2,%3},{%4,%5,%6,%7},{%8,%9},{%0,%1,%2,%3};"
        : "+f"(d[0]), "+f"(d[1]), "+f"(d[2]), "+f"(d[3])
        : "r"(__float_as_uint(aa.x)), "r"(__float_as_uint(ab.x)),
          "r"(__float_as_uint(aa.y)), "r"(__float_as_uint(ab.y)),
          "r"(__float_as_uint(bb.x)), "r"(__float_as_uint(bb.y)));
}

// ---------------- precompute kernels ----------------
__global__ void prep_kt(const float* __restrict__ mk) {
    int i = blockIdx.x * blockDim.x + threadIdx.x;      // over BSZ*64*NTOT
    if (i >= BSZ * 64 * NTOT) return;
    int n  = i & (NTOT - 1);
    int ck = (i >> 13) & 63;
    int b  = i >> 19;
    float v = mk[i];
    int h = ck >> 4, c = ck & 15;
    size_t base = ((size_t)(b * HEADS_N + h) * NTOT + n) * 32;
    g_Kt[base + permk(c)]      = rn_tf32(v * v * v);
    g_Kt[base + permk(16 + c)] = rn_tf32(v);
}

__global__ void prep_q(const float* __restrict__ qk, const float* __restrict__ qe) {
    int i = blockIdx.x * blockDim.x + threadIdx.x;      // over BSZ*4*MTOT
    if (i >= BSZ * HEADS_N * MTOT) return;
    int m = i & (MTOT - 1);
    int h = (i >> 10) & 3;
    int b = i >> 12;
    size_t qb = (size_t)i * 32;
    float bias = 0.0f;
    #pragma unroll
    for (int c = 0; c < 16; c++) {
        size_t gi = ((size_t)(b * 64 + h * 16 + c)) * MTOT + m;
        float e = qe[gi];
        float k = qk[gi];
        g_Q[qb + permk(c)]      = rn_tf32(-e);
        g_Q[qb + permk(16 + c)] = rn_tf32(2.0f * k * e);
        bias += e * k * k * k;
    }
    g_bias[i] = bias;
}

// ---------------- main fused kernel ----------------
__global__ void __launch_bounds__(NTHREADS, 1)
mr_main(const float* __restrict__ mv, const float* __restrict__ ms)
{
    extern __shared__ float sm[];
    const int tid  = threadIdx.x;
    const int w    = tid >> 5;
    const int lane = tid & 31;
    const int gid  = lane >> 2;      // 0..7
    const int tig  = lane & 3;       // 0..3

    const int bx    = blockIdx.x;    // 128 blocks
    const int split = bx & 3;
    const int mtile = (bx >> 2) & 15;
    const int b     = bx >> 6;
    const int m0    = mtile * M_T;
    const int nbase = split * NPS;

    // ---- stage bias + Q (block-constant) ----
    if (tid < 256)
        sm[F_BIAS + tid] = g_bias[(size_t)(b * HEADS_N + (tid >> 6)) * MTOT + m0 + (tid & 63)];
    {
        const float4* src = (const float4*)(g_Q + (size_t)(b * HEADS_N) * MTOT * 32);
        #pragma unroll
        for (int it = 0; it < 4; it++) {
            int j = tid + it * NTHREADS;         // 2048 float4
            int kq = j & 7, mm = (j >> 3) & 63, h = j >> 9;
            float4 v = src[((size_t)h * MTOT + m0 + mm) * 8 + kq];
            *(float4*)(sm + F_Q + (h * 64 + mm) * 36 + kq * 4) = v;
        }
    }

    // Phase A mapping
    const int hA  = w >> 2;
    const int n0w = (w & 3) * 16;
    // Phase B mapping
    const int cv0   = (w & 7) * 16;
    const int mhalf = (w >> 3) * 32;

    float acc[4][4][4];   // [h][mt][reg]
    #pragma unroll
    for (int h = 0; h < 4; h++)
        #pragma unroll
        for (int mt = 0; mt < 4; mt++)
            #pragma unroll
            for (int r = 0; r < 4; r++) acc[h][mt][r] = 0.0f;

    __syncthreads();

    for (int chunk = 0; chunk < NCHUNKS; chunk++) {
        const int n0 = nbase + chunk * NCH;

        // ---- stage Kt chunk [4h][64n][36] ----
        {
            const float4* src = (const float4*)(g_Kt + (size_t)(b * HEADS_N) * NTOT * 32);
            #pragma unroll
            for (int it = 0; it < 4; it++) {
                int j = tid + it * NTHREADS;     // 2048 float4
                int kq = j & 7, nn = (j >> 3) & 63, h = j >> 9;
                float4 v = src[((size_t)h * NTOT + n0 + nn) * 8 + kq];
                *(float4*)(sm + F_KT + (h * 64 + nn) * 36 + kq * 4) = v;
            }
        }
        if (tid < 64) {
            // ms staged at permuted position so softmax reads linearly
            sm[F_MS + permk(tid)] = ms[(size_t)b * NTOT + n0 + tid];
        }
        __syncthreads();

        // ---- Phase A: S[n][m] per head, 2 passes of 4 m-tiles ----
        {
            const float* ktb = sm + F_KT + hA * 64 * 36;
            const float* qb  = sm + F_Q  + hA * 64 * 36;
            const int pos0 = n0w + ((gid & 3) << 1) + (gid >> 2);
            const int pos1 = pos0 + 8;
            #pragma unroll
            for (int pass = 0; pass < 2; pass++) {
                float sacc[4][4];
                #pragma unroll
                for (int mt = 0; mt < 4; mt++)
                    #pragma unroll
                    for (int r = 0; r < 4; r++) sacc[mt][r] = 0.0f;
                #pragma unroll
                for (int ks = 0; ks < 4; ks++) {
                    float2 aa = *(const float2*)(ktb + (n0w + gid) * 36 + ks * 8 + 2 * tig);
                    float2 ab = *(const float2*)(ktb + (n0w + gid + 8) * 36 + ks * 8 + 2 * tig);
                    #pragma unroll
                    for (int mt = 0; mt < 4; mt++) {
                        int m = (pass * 4 + mt) * 8 + gid;
                        float2 bb = *(const float2*)(qb + m * 36 + ks * 8 + 2 * tig);
                        mma_tf32(sacc[mt], aa, ab, bb);
                    }
                }
                #pragma unroll
                for (int mt = 0; mt < 4; mt++) {
                    int mcol = (pass * 4 + mt) * 8 + 2 * tig;
                    float* sp = sm + F_SP + (hA * 64 + mcol) * 68;
                    sp[pos0]      = sacc[mt][0];
                    sp[68 + pos0] = sacc[mt][1];
                    sp[pos1]      = sacc[mt][2];
                    sp[68 + pos1] = sacc[mt][3];
                }
            }
        }
        __syncthreads();

        // ---- softmax over heads, in place, write tf32 probs ----
        #pragma unroll
        for (int it = 0; it < 2; it++) {
            int i = tid + it * NTHREADS;         // 1024 groups: [64m][16 pos4]
            int m = i >> 4, p4 = i & 15;
            float4 v0 = *(float4*)(sm + F_SP + ((0 * 64 + m) * 68) + p4 * 4);
            float4 v1 = *(float4*)(sm + F_SP + ((1 * 64 + m) * 68) + p4 * 4);
            float4 v2 = *(float4*)(sm + F_SP + ((2 * 64 + m) * 68) + p4 * 4);
            float4 v3 = *(float4*)(sm + F_SP + ((3 * 64 + m) * 68) + p4 * 4);
            float4 mv4 = *(float4*)(sm + F_MS + p4 * 4);
            float b0 = sm[F_BIAS + 0 * 64 + m];
            float b1 = sm[F_BIAS + 1 * 64 + m];
            float b2 = sm[F_BIAS + 2 * 64 + m];
            float b3 = sm[F_BIAS + 3 * 64 + m];
            #pragma unroll
            for (int c = 0; c < 4; c++) {
                float msv = (&mv4.x)[c];
                float s0 = ((&v0.x)[c] - b0) * msv * 0.125f;
                float s1 = ((&v1.x)[c] - b1) * msv * 0.125f;
                float s2 = ((&v2.x)[c] - b2) * msv * 0.125f;
                float s3 = ((&v3.x)[c] - b3) * msv * 0.125f;
                float mx = fmaxf(fmaxf(s0, s1), fmaxf(s2, s3));
                float e0 = __expf(s0 - mx), e1 = __expf(s1 - mx);
                float e2 = __expf(s2 - mx), e3 = __expf(s3 - mx);
                float inv = __fdividef(1.0f, e0 + e1 + e2 + e3);
                (&v0.x)[c] = rn_tf32(e0 * inv);
                (&v1.x)[c] = rn_tf32(e1 * inv);
                (&v2.x)[c] = rn_tf32(e2 * inv);
                (&v3.x)[c] = rn_tf32(e3 * inv);
            }
            *(float4*)(sm + F_SP + ((0 * 64 + m) * 68) + p4 * 4) = v0;
            *(float4*)(sm + F_SP + ((1 * 64 + m) * 68) + p4 * 4) = v1;
            *(float4*)(sm + F_SP + ((2 * 64 + m) * 68) + p4 * 4) = v2;
            *(float4*)(sm + F_SP + ((3 * 64 + m) * 68) + p4 * 4) = v3;
        }
        __syncthreads();

        // ---- Phase B: per head, stage mv then accumulate O ----
        for (int h = 0; h < HEADS_N; h++) {
            // stage mv head tile [128cv][64n perm], tf32-rounded, pair STS.64
            const float* srcb = mv + ((size_t)(b * CVTOT + h * 128)) * NTOT + n0;
            #pragma unroll
            for (int it = 0; it < 8; it++) {
                int j = tid + it * NTHREADS;     // 4096 pairs
                int q = j & 3, g = (j >> 2) & 7, cv = j >> 5;
                const float* s = srcb + (size_t)cv * NTOT + g * 8 + q;
                float2 v;
                v.x = rn_tf32(s[0]);
                v.y = rn_tf32(s[4]);
                *(float2*)(sm + F_MV + cv * 68 + g * 8 + 2 * q) = v;
            }
            __syncthreads();

            const float* spb = sm + F_SP + h * 64 * 68;
            #pragma unroll
            for (int ks = 0; ks < 8; ks++) {
                float2 aa = *(const float2*)(sm + F_MV + (cv0 + gid) * 68 + ks * 8 + 2 * tig);
                float2 ab = *(const float2*)(sm + F_MV + (cv0 + gid + 8) * 68 + ks * 8 + 2 * tig);
                #pragma unroll
                for (int mt = 0; mt < 4; mt++) {
                    int m = mhalf + mt * 8 + gid;
                    float2 bb = *(const float2*)(spb + m * 68 + ks * 8 + 2 * tig);
                    mma_tf32(acc[h][mt], aa, ab, bb);
                }
            }
            __syncthreads();
        }
    }

    // ---- writeout: fragment-direct STG.64 into g_partial ----
    {
        float* ppb = g_partial + ((size_t)(split * BSZ + b) * CVTOT) * MTOT + m0;
        #pragma unroll
        for (int h = 0; h < 4; h++) {
            float* pp = ppb + (size_t)(h * 128) * MTOT;
            #pragma unroll
            for (int mt = 0; mt < 4; mt++) {
                int mloc = mhalf + mt * 8 + 2 * tig;
                float2 lo = { acc[h][mt][0], acc[h][mt][1] };
                float2 hi = { acc[h][mt][2], acc[h][mt][3] };
                *(float2*)(pp + (size_t)(cv0 + gid) * MTOT + mloc)     = lo;
                *(float2*)(pp + (size_t)(cv0 + gid + 8) * MTOT + mloc) = hi;
            }
        }
    }
}

// ---------------- assemble: reduce splits + copy qv ----------------
__global__ void assemble_kernel(const float* __restrict__ qv, float* __restrict__ out)
{
    const int total4 = BSZ * 2 * CVTOT * MTOT / 4;
    int idx = blockIdx.x * blockDim.x + threadIdx.x;
    if (idx >= total4) return;
    int gf  = idx * 4;
    int b   = gf >> 20;
    int rem = gf & ((1 << 20) - 1);
    int ch  = rem >> 10;
    int m   = rem & 1023;

    float4 r;
    if (ch < CVTOT) {
        const size_t stride = (size_t)BSZ * CVTOT * MTOT;
        size_t off = ((size_t)b * CVTOT + ch) * MTOT + m;
        float4 a0 = *reinterpret_cast<const float4*>(g_partial + 0 * stride + off);
        float4 a1 = *reinterpret_cast<const float4*>(g_partial + 1 * stride + off);
        float4 a2 = *reinterpret_cast<const float4*>(g_partial + 2 * stride + off);
        float4 a3 = *reinterpret_cast<const float4*>(g_partial + 3 * stride + off);
        r.x = a0.x + a1.x + a2.x + a3.x;
        r.y = a0.y + a1.y + a2.y + a3.y;
        r.z = a0.z + a1.z + a2.z + a3.z;
        r.w = a0.w + a1.w + a2.w + a3.w;
    } else {
        r = *reinterpret_cast<const float4*>(
                qv + ((size_t)b * CVTOT + (ch - CVTOT)) * MTOT + m);
    }
    *reinterpret_cast<float4*>(out + (size_t)gf) = r;
}

extern "C" void kernel_launch(void* const* d_in, const int* in_sizes, int n_in,
                              void* d_out, int out_size)
{
    const float* mk = (const float*)d_in[0];
    const float* qk = (const float*)d_in[1];
    const float* ms = (const float*)d_in[2];
    const float* qe = (const float*)d_in[3];
    const float* mv = (const float*)d_in[4];
    const float* qv = (const float*)d_in[5];
    float* out = (float*)d_out;

    prep_kt<<<(BSZ * 64 * NTOT + 255) / 256, 256>>>(mk);
    prep_q<<<(BSZ * HEADS_N * MTOT + 255) / 256, 256>>>(qk, qe);

    cudaFuncSetAttribute(mr_main, cudaFuncAttributeMaxDynamicSharedMemorySize,
                         SM_TOTAL);
    mr_main<<<BSZ * 16 * NSPLIT, NTHREADS, SM_TOTAL>>>(mv, ms);

    const int total4 = BSZ * 2 * CVTOT * MTOT / 4;
    assemble_kernel<<<(total4 + 255) / 256, 256>>>(qv, out);
}

// round 7
// speedup vs baseline: 1.4311x; 1.4311x over previous
#include <cuda_runtime.h>
#include <cstdint>

// ---------------- problem constants ----------------
#define HEADS_N 4
#define BSZ 2
#define NTOT 8192        // THW
#define MTOT 1024        // HW
#define CVTOT 512
#define M_T 64           // m-tile per block
#define NSPLIT 4
#define NPS (NTOT / NSPLIT)     // 2048
#define NCH 64                  // n per chunk
#define NCHUNKS (NPS / NCH)     // 32
#define NTHREADS 512

// ---------------- device scratch (no cudaMalloc allowed) ----------------
__device__ __align__(16) float g_partial[NSPLIT * BSZ * CVTOT * MTOT]; // 16 MB
__device__ __align__(16) float g_Kt[BSZ * HEADS_N * NTOT * 32];        // [b][h][n][32k perm] 8 MB
__device__ __align__(16) float g_Q [BSZ * HEADS_N * MTOT * 32];        // [b][h][m][32k perm] 1 MB
__device__ __align__(16) float g_bias[BSZ * HEADS_N * MTOT];           // 32 KB
__device__ __align__(16) float g_mvp[BSZ * CVTOT * NTOT];              // tf32, n-permuted, 33.5 MB

// ---------------- smem layout (float offsets) ----------------
// bias[4][64] @0 ; ms[64] @256 ; Q[4][64][36] @320 ; Kt[4][64][36] @9536 ;
// P[4][64][68] @18752 ; total 36160 floats = 144640 B
#define F_BIAS 0
#define F_MS   256
#define F_Q    320
#define F_KT   (F_Q + 4 * 64 * 36)      // 9536
#define F_P    (F_KT + 4 * 64 * 36)     // 18752
#define SM_TOTAL ((F_P + 4 * 64 * 68) * 4)

// ---------------- helpers ----------------
__device__ __host__ __forceinline__ int permk(int k) {
    // within-8 order [0,4,1,5,2,6,3,7]: slot = 2*(k%4) + (k%8)/4
    return (k & ~7) | ((k & 3) << 1) | ((k & 7) >> 2);
}
__device__ __forceinline__ float rn_tf32(float x) {
    uint32_t u;
    asm("cvt.rna.tf32.f32 %0, %1;" : "=r"(u) : "f"(x));
    return __uint_as_float(u);
}
__device__ __forceinline__ void mma_tf32(float* d, float2 aa, float2 ab, float2 bb) {
    asm volatile(
        "mma.sync.aligned.m16n8k8.row.col.f32.tf32.tf32.f32 "
        "{%0,%1,%2,%3},{%4,%5,%6,%7},{%8,%9},{%0,%1,%2,%3};"
        : "+f"(d[0]), "+f"(d[1]), "+f"(d[2]), "+f"(d[3])
        : "r"(__float_as_uint(aa.x)), "r"(__float_as_uint(ab.x)),
          "r"(__float_as_uint(aa.y)), "r"(__float_as_uint(ab.y)),
          "r"(__float_as_uint(bb.x)), "r"(__float_as_uint(bb.y)));
}

// ---------------- precompute kernels ----------------
__global__ void prep_kt(const float* __restrict__ mk) {
    int i = blockIdx.x * blockDim.x + threadIdx.x;      // over BSZ*64*NTOT
    if (i >= BSZ * 64 * NTOT) return;
    int n  = i & (NTOT - 1);
    int ck = (i >> 13) & 63;
    int b  = i >> 19;
    float v = mk[i];
    int h = ck >> 4, c = ck & 15;
    size_t base = ((size_t)(b * HEADS_N + h) * NTOT + n) * 32;
    g_Kt[base + permk(c)]      = rn_tf32(v * v * v);
    g_Kt[base + permk(16 + c)] = rn_tf32(v);
}

__global__ void prep_q(const float* __restrict__ qk, const float* __restrict__ qe) {
    int i = blockIdx.x * blockDim.x + threadIdx.x;      // over BSZ*4*MTOT
    if (i >= BSZ * HEADS_N * MTOT) return;
    int m = i & (MTOT - 1);
    int h = (i >> 10) & 3;
    int b = i >> 12;
    size_t qb = (size_t)i * 32;
    float bias = 0.0f;
    #pragma unroll
    for (int c = 0; c < 16; c++) {
        size_t gi = ((size_t)(b * 64 + h * 16 + c)) * MTOT + m;
        float e = qe[gi];
        float k = qk[gi];
        g_Q[qb + permk(c)]      = rn_tf32(-e);
        g_Q[qb + permk(16 + c)] = rn_tf32(2.0f * k * e);
        bias += e * k * k * k;
    }
    g_bias[i] = bias;
}

__global__ void prep_mv(const float* __restrict__ mv) {
    int i = blockIdx.x * blockDim.x + threadIdx.x;      // over BSZ*CVTOT*NTOT
    if (i >= BSZ * CVTOT * NTOT) return;
    int n   = i & (NTOT - 1);
    int row = i >> 13;
    g_mvp[(size_t)row * NTOT + permk(n)] = rn_tf32(mv[i]);
}

// ---------------- main fused kernel ----------------
__global__ void __launch_bounds__(NTHREADS, 1)
mr_main(const float* __restrict__ ms)
{
    extern __shared__ float sm[];
    const int tid  = threadIdx.x;
    const int w    = tid >> 5;
    const int lane = tid & 31;
    const int gid  = lane >> 2;      // 0..7
    const int tig  = lane & 3;       // 0..3

    const int bx    = blockIdx.x;    // 128 blocks
    const int split = bx & 3;
    const int mtile = (bx >> 2) & 15;
    const int b     = bx >> 6;
    const int m0    = mtile * M_T;
    const int nbase = split * NPS;

    // ---- stage bias + Q (block-constant) ----
    if (tid < 256)
        sm[F_BIAS + tid] = g_bias[(size_t)(b * HEADS_N + (tid >> 6)) * MTOT + m0 + (tid & 63)];
    {
        const float4* src = (const float4*)(g_Q + (size_t)(b * HEADS_N) * MTOT * 32);
        #pragma unroll
        for (int it = 0; it < 4; it++) {
            int j = tid + it * NTHREADS;         // 2048 float4
            int kq = j & 7, mm = (j >> 3) & 63, h = j >> 9;
            float4 v = src[((size_t)h * MTOT + m0 + mm) * 8 + kq];
            *(float4*)(sm + F_Q + (h * 64 + mm) * 36 + kq * 4) = v;
        }
    }

    // Phase A mapping: warp = (ntile, mtile4), all 4 heads in-register
    const int nt  = w & 3;
    const int mA0 = (w >> 2) * 16;
    const int nA  = nt * 16 + gid;
    // Phase B mapping: one head per warp, cv32 x m64
    const int headB = w >> 2;
    const int cvg   = w & 3;

    float acc[2][8][4];   // O accumulators [cvtile][mt][reg]
    #pragma unroll
    for (int rt = 0; rt < 2; rt++)
        #pragma unroll
        for (int mt = 0; mt < 8; mt++)
            #pragma unroll
            for (int r = 0; r < 4; r++) acc[rt][mt][r] = 0.0f;

    const float* gv = g_mvp + (size_t)(b * CVTOT + headB * 128 + cvg * 32) * NTOT;
    const float* pb = sm + F_P + headB * 4352;

    for (int chunk = 0; chunk < NCHUNKS; chunk++) {
        const int n0 = nbase + chunk * NCH;

        // ---- stage Kt chunk [4h][64n][36] + ms (logical order) ----
        {
            const float4* src = (const float4*)(g_Kt + (size_t)(b * HEADS_N) * NTOT * 32);
            #pragma unroll
            for (int it = 0; it < 4; it++) {
                int j = tid + it * NTHREADS;     // 2048 float4
                int kq = j & 7, nn = (j >> 3) & 63, h = j >> 9;
                float4 v = src[((size_t)h * NTOT + n0 + nn) * 8 + kq];
                *(float4*)(sm + F_KT + (h * 64 + nn) * 36 + kq * 4) = v;
            }
        }
        if (tid < 64) sm[F_MS + tid] = ms[(size_t)b * NTOT + n0 + tid];
        __syncthreads();

        // ---- Phase A: S for all 4 heads, 16n x 16m tile per warp ----
        float sacc[4][2][4];
        #pragma unroll
        for (int h = 0; h < 4; h++)
            #pragma unroll
            for (int j = 0; j < 2; j++)
                #pragma unroll
                for (int r = 0; r < 4; r++) sacc[h][j][r] = 0.0f;

        #pragma unroll
        for (int ks = 0; ks < 4; ks++) {
            #pragma unroll
            for (int h = 0; h < 4; h++) {
                const float* ktb = sm + F_KT + h * 2304;
                const float* qb  = sm + F_Q  + h * 2304;
                float2 aa = *(const float2*)(ktb + nA * 36 + ks * 8 + 2 * tig);
                float2 ab = *(const float2*)(ktb + (nA + 8) * 36 + ks * 8 + 2 * tig);
                #pragma unroll
                for (int j = 0; j < 2; j++) {
                    float2 bb = *(const float2*)(qb + (mA0 + j * 8 + gid) * 36 + ks * 8 + 2 * tig);
                    mma_tf32(sacc[h][j], aa, ab, bb);
                }
            }
        }

        // ---- softmax over heads, entirely in registers ----
        {
            const float msa = sm[F_MS + nA] * 0.125f;
            const float msb = sm[F_MS + nA + 8] * 0.125f;
            #pragma unroll
            for (int j = 0; j < 2; j++) {
                #pragma unroll
                for (int c = 0; c < 2; c++) {
                    int m = mA0 + j * 8 + 2 * tig + c;
                    float b0 = sm[F_BIAS + m];
                    float b1 = sm[F_BIAS + 64 + m];
                    float b2 = sm[F_BIAS + 128 + m];
                    float b3 = sm[F_BIAS + 192 + m];
                    // n_a position (reg index c)
                    {
                        float s0 = (sacc[0][j][c] - b0) * msa;
                        float s1 = (sacc[1][j][c] - b1) * msa;
                        float s2 = (sacc[2][j][c] - b2) * msa;
                        float s3 = (sacc[3][j][c] - b3) * msa;
                        float mx = fmaxf(fmaxf(s0, s1), fmaxf(s2, s3));
                        float e0 = __expf(s0 - mx), e1 = __expf(s1 - mx);
                        float e2 = __expf(s2 - mx), e3 = __expf(s3 - mx);
                        float inv = __fdividef(1.0f, e0 + e1 + e2 + e3);
                        sacc[0][j][c] = rn_tf32(e0 * inv);
                        sacc[1][j][c] = rn_tf32(e1 * inv);
                        sacc[2][j][c] = rn_tf32(e2 * inv);
                        sacc[3][j][c] = rn_tf32(e3 * inv);
                    }
                    // n_b position (reg index 2+c)
                    {
                        float s0 = (sacc[0][j][2 + c] - b0) * msb;
                        float s1 = (sacc[1][j][2 + c] - b1) * msb;
                        float s2 = (sacc[2][j][2 + c] - b2) * msb;
                        float s3 = (sacc[3][j][2 + c] - b3) * msb;
                        float mx = fmaxf(fmaxf(s0, s1), fmaxf(s2, s3));
                        float e0 = __expf(s0 - mx), e1 = __expf(s1 - mx);
                        float e2 = __expf(s2 - mx), e3 = __expf(s3 - mx);
                        float inv = __fdividef(1.0f, e0 + e1 + e2 + e3);
                        sacc[0][j][2 + c] = rn_tf32(e0 * inv);
                        sacc[1][j][2 + c] = rn_tf32(e1 * inv);
                        sacc[2][j][2 + c] = rn_tf32(e2 * inv);
                        sacc[3][j][2 + c] = rn_tf32(e3 * inv);
                    }
                }
            }
        }

        // ---- scatter-store P[h][m][n_perm] (conflict-free banks) ----
        {
            const int pos0 = nt * 16 + ((gid & 3) << 1) + (gid >> 2);
            #pragma unroll
            for (int h = 0; h < 4; h++) {
                #pragma unroll
                for (int j = 0; j < 2; j++) {
                    float* sp = sm + F_P + h * 4352 + (mA0 + j * 8 + 2 * tig) * 68;
                    sp[pos0]          = sacc[h][j][0];
                    sp[68 + pos0]     = sacc[h][j][1];
                    sp[pos0 + 8]      = sacc[h][j][2];
                    sp[68 + pos0 + 8] = sacc[h][j][3];
                }
            }
        }
        __syncthreads();

        // ---- Phase B: O += mv * P ; mv A-fragments direct from L2 ----
        #pragma unroll
        for (int ks = 0; ks < 8; ks++) {
            const int co = n0 + ks * 8 + 2 * tig;
            float2 a0 = *(const float2*)(gv + (size_t)gid * NTOT + co);
            float2 a1 = *(const float2*)(gv + (size_t)(gid + 8) * NTOT + co);
            float2 a2 = *(const float2*)(gv + (size_t)(gid + 16) * NTOT + co);
            float2 a3 = *(const float2*)(gv + (size_t)(gid + 24) * NTOT + co);
            #pragma unroll
            for (int mt = 0; mt < 8; mt++) {
                float2 bb = *(const float2*)(pb + (mt * 8 + gid) * 68 + ks * 8 + 2 * tig);
                mma_tf32(acc[0][mt], a0, a1, bb);
                mma_tf32(acc[1][mt], a2, a3, bb);
            }
        }
        __syncthreads();
    }

    // ---- writeout: fragment-direct STG.64 into g_partial ----
    {
        float* pp = g_partial +
            ((size_t)(split * BSZ + b) * CVTOT + headB * 128 + cvg * 32) * MTOT + m0;
        #pragma unroll
        for (int rt = 0; rt < 2; rt++) {
            #pragma unroll
            for (int mt = 0; mt < 8; mt++) {
                int r0 = rt * 16 + gid;
                int m  = mt * 8 + 2 * tig;
                float2 lo = { acc[rt][mt][0], acc[rt][mt][1] };
                float2 hi = { acc[rt][mt][2], acc[rt][mt][3] };
                *(float2*)(pp + (size_t)r0 * MTOT + m)       = lo;
                *(float2*)(pp + (size_t)(r0 + 8) * MTOT + m) = hi;
            }
        }
    }
}

// ---------------- assemble: reduce splits + copy qv ----------------
__global__ void assemble_kernel(const float* __restrict__ qv, float* __restrict__ out)
{
    const int total4 = BSZ * 2 * CVTOT * MTOT / 4;
    int idx = blockIdx.x * blockDim.x + threadIdx.x;
    if (idx >= total4) return;
    int gf  = idx * 4;
    int b   = gf >> 20;
    int rem = gf & ((1 << 20) - 1);
    int ch  = rem >> 10;
    int m   = rem & 1023;

    float4 r;
    if (ch < CVTOT) {
        const size_t stride = (size_t)BSZ * CVTOT * MTOT;
        size_t off = ((size_t)b * CVTOT + ch) * MTOT + m;
        float4 a0 = *reinterpret_cast<const float4*>(g_partial + 0 * stride + off);
        float4 a1 = *reinterpret_cast<const float4*>(g_partial + 1 * stride + off);
        float4 a2 = *reinterpret_cast<const float4*>(g_partial + 2 * stride + off);
        float4 a3 = *reinterpret_cast<const float4*>(g_partial + 3 * stride + off);
        r.x = a0.x + a1.x + a2.x + a3.x;
        r.y = a0.y + a1.y + a2.y + a3.y;
        r.z = a0.z + a1.z + a2.z + a3.z;
        r.w = a0.w + a1.w + a2.w + a3.w;
    } else {
        r = *reinterpret_cast<const float4*>(
                qv + ((size_t)b * CVTOT + (ch - CVTOT)) * MTOT + m);
    }
    *reinterpret_cast<float4*>(out + (size_t)gf) = r;
}

extern "C" void kernel_launch(void* const* d_in, const int* in_sizes, int n_in,
                              void* d_out, int out_size)
{
    const float* mk = (const float*)d_in[0];
    const float* qk = (const float*)d_in[1];
    const float* ms = (const float*)d_in[2];
    const float* qe = (const float*)d_in[3];
    const float* mv = (const float*)d_in[4];
    const float* qv = (const float*)d_in[5];
    float* out = (float*)d_out;

    prep_kt<<<(BSZ * 64 * NTOT + 255) / 256, 256>>>(mk);
    prep_q<<<(BSZ * HEADS_N * MTOT + 255) / 256, 256>>>(qk, qe);
    prep_mv<<<(BSZ * CVTOT * NTOT + 255) / 256, 256>>>(mv);

    cudaFuncSetAttribute(mr_main, cudaFuncAttributeMaxDynamicSharedMemorySize,
                         SM_TOTAL);
    mr_main<<<BSZ * 16 * NSPLIT, NTHREADS, SM_TOTAL>>>(ms);

    const int total4 = BSZ * 2 * CVTOT * MTOT / 4;
    assemble_kernel<<<(total4 + 255) / 256, 256>>>(qv, out);
}

// round 8
// speedup vs baseline: 1.5907x; 1.1116x over previous
#include <cuda_runtime.h>
#include <cstdint>

// ---------------- problem constants ----------------
#define HEADS_N 4
#define BSZ 2
#define NTOT 8192        // THW
#define MTOT 1024        // HW
#define CVTOT 512
#define M_T 64           // m-tile per block
#define NSPLIT 4
#define NPS (NTOT / NSPLIT)     // 2048
#define NCH 64                  // n per chunk
#define NCHUNKS (NPS / NCH)     // 32
#define NTHREADS 512

// ---------------- device scratch (no cudaMalloc allowed) ----------------
__device__ __align__(16) float g_partial[NSPLIT * BSZ * CVTOT * MTOT]; // 16 MB
__device__ __align__(16) float g_Kt[BSZ * HEADS_N * NTOT * 32];        // [b][h][n][32k perm] 8 MB
__device__ __align__(16) float g_Q [BSZ * HEADS_N * MTOT * 32];        // [b][h][m][32k perm] 1 MB
__device__ __align__(16) float g_bias[BSZ * HEADS_N * MTOT];           // 32 KB
// mv in fragment-native layout: [b][cvblk(16)][ngrp(1024)][half(2)][lane(32)][4]
__device__ __align__(16) float g_mvp[BSZ * CVTOT * NTOT];              // 33.5 MB

// ---------------- smem layout (float offsets) ----------------
#define F_BIAS 0
#define F_MS   256
#define F_Q    320
#define F_KT   (F_Q + 4 * 64 * 36)      // 9536
#define F_P    (F_KT + 4 * 64 * 36)     // 18752
#define SM_TOTAL ((F_P + 4 * 64 * 68) * 4)

// ---------------- helpers ----------------
__device__ __host__ __forceinline__ int permk(int k) {
    // within-8 order [0,4,1,5,2,6,3,7]: slot = 2*(k%4) + (k%8)/4
    return (k & ~7) | ((k & 3) << 1) | ((k & 7) >> 2);
}
__device__ __forceinline__ float rn_tf32(float x) {
    uint32_t u;
    asm("cvt.rna.tf32.f32 %0, %1;" : "=r"(u) : "f"(x));
    return __uint_as_float(u);
}
__device__ __forceinline__ void mma_tf32(float* d, float2 aa, float2 ab, float2 bb) {
    asm volatile(
        "mma.sync.aligned.m16n8k8.row.col.f32.tf32.tf32.f32 "
        "{%0,%1,%2,%3},{%4,%5,%6,%7},{%8,%9},{%0,%1,%2,%3};"
        : "+f"(d[0]), "+f"(d[1]), "+f"(d[2]), "+f"(d[3])
        : "r"(__float_as_uint(aa.x)), "r"(__float_as_uint(ab.x)),
          "r"(__float_as_uint(aa.y)), "r"(__float_as_uint(ab.y)),
          "r"(__float_as_uint(bb.x)), "r"(__float_as_uint(bb.y)));
}

// ---------------- precompute kernels ----------------
__global__ void prep_kt(const float* __restrict__ mk) {
    int i = blockIdx.x * blockDim.x + threadIdx.x;      // over BSZ*64*NTOT
    if (i >= BSZ * 64 * NTOT) return;
    int n  = i & (NTOT - 1);
    int ck = (i >> 13) & 63;
    int b  = i >> 19;
    float v = mk[i];
    int h = ck >> 4, c = ck & 15;
    size_t base = ((size_t)(b * HEADS_N + h) * NTOT + n) * 32;
    g_Kt[base + permk(c)]      = rn_tf32(v * v * v);
    g_Kt[base + permk(16 + c)] = rn_tf32(v);
}

__global__ void prep_q(const float* __restrict__ qk, const float* __restrict__ qe) {
    int i = blockIdx.x * blockDim.x + threadIdx.x;      // over BSZ*4*MTOT
    if (i >= BSZ * HEADS_N * MTOT) return;
    int m = i & (MTOT - 1);
    int h = (i >> 10) & 3;
    int b = i >> 12;
    size_t qb = (size_t)i * 32;
    float bias = 0.0f;
    #pragma unroll
    for (int c = 0; c < 16; c++) {
        size_t gi = ((size_t)(b * 64 + h * 16 + c)) * MTOT + m;
        float e = qe[gi];
        float k = qk[gi];
        g_Q[qb + permk(c)]      = rn_tf32(-e);
        g_Q[qb + permk(16 + c)] = rn_tf32(2.0f * k * e);
        bias += e * k * k * k;
    }
    g_bias[i] = bias;
}

// fragment-native mv layout: one warp's per-ks fragment set is two contiguous
// 512B blocks. float offset =
//   ((b*16+blk)*1024 + ngrp)*256 + half*128 + (gid*4+tig)*4 + (rr&1)*2 + parity
__global__ void prep_mv(const float* __restrict__ mv) {
    int i = blockIdx.x * blockDim.x + threadIdx.x;      // over BSZ*CVTOT*NTOT
    if (i >= BSZ * CVTOT * NTOT) return;
    int n   = i & (NTOT - 1);
    int row = i >> 13;            // b*512 + cv
    int b   = row >> 9;
    int cv  = row & 511;
    int blk = cv >> 5, r = cv & 31;
    int gid = r & 7, rr = r >> 3;
    int ngrp = n >> 3;
    int slot = ((n & 3) << 1) | ((n & 7) >> 2);
    int tig = slot >> 1, par = slot & 1;
    size_t off = (((size_t)(b * 16 + blk) * (NTOT / 8) + ngrp) << 8)
               + ((size_t)(rr >> 1) << 7) + ((gid * 4 + tig) << 2)
               + ((rr & 1) << 1) + par;
    g_mvp[off] = rn_tf32(mv[i]);
}

// ---------------- main fused kernel ----------------
__global__ void __launch_bounds__(NTHREADS, 1)
mr_main(const float* __restrict__ ms)
{
    extern __shared__ float sm[];
    const int tid  = threadIdx.x;
    const int w    = tid >> 5;
    const int lane = tid & 31;
    const int gid  = lane >> 2;      // 0..7
    const int tig  = lane & 3;       // 0..3

    const int bx    = blockIdx.x;    // 128 blocks
    const int split = bx & 3;
    const int mtile = (bx >> 2) & 15;
    const int b     = bx >> 6;
    const int m0    = mtile * M_T;
    const int nbase = split * NPS;

    // ---- stage bias + Q (block-constant) ----
    if (tid < 256)
        sm[F_BIAS + tid] = g_bias[(size_t)(b * HEADS_N + (tid >> 6)) * MTOT + m0 + (tid & 63)];
    {
        const float4* src = (const float4*)(g_Q + (size_t)(b * HEADS_N) * MTOT * 32);
        #pragma unroll
        for (int it = 0; it < 4; it++) {
            int j = tid + it * NTHREADS;         // 2048 float4
            int kq = j & 7, mm = (j >> 3) & 63, h = j >> 9;
            float4 v = src[((size_t)h * MTOT + m0 + mm) * 8 + kq];
            *(float4*)(sm + F_Q + (h * 64 + mm) * 36 + kq * 4) = v;
        }
    }

    // Phase A mapping: warp = (ntile, mtile4), all 4 heads in-register
    const int nt  = w & 3;
    const int mA0 = (w >> 2) * 16;
    const int nA  = nt * 16 + gid;
    // Phase B mapping: one head per warp, cv32 x m64
    const int headB = w >> 2;
    const int cvg   = w & 3;

    float acc[2][8][4];   // O accumulators [cvtile][mt][reg]
    #pragma unroll
    for (int rt = 0; rt < 2; rt++)
        #pragma unroll
        for (int mt = 0; mt < 8; mt++)
            #pragma unroll
            for (int r = 0; r < 4; r++) acc[rt][mt][r] = 0.0f;

    // fragment-native mv base for this warp's 32-cv block
    const float* gvf = g_mvp +
        (((size_t)(b * 16 + headB * 4 + cvg)) * (NTOT / 8)) * 256;
    const float* pb = sm + F_P + headB * 4352;

    for (int chunk = 0; chunk < NCHUNKS; chunk++) {
        const int n0 = nbase + chunk * NCH;

        // ---- stage Kt chunk [4h][64n][36] + ms (logical order) ----
        {
            const float4* src = (const float4*)(g_Kt + (size_t)(b * HEADS_N) * NTOT * 32);
            #pragma unroll
            for (int it = 0; it < 4; it++) {
                int j = tid + it * NTHREADS;     // 2048 float4
                int kq = j & 7, nn = (j >> 3) & 63, h = j >> 9;
                float4 v = src[((size_t)h * NTOT + n0 + nn) * 8 + kq];
                *(float4*)(sm + F_KT + (h * 64 + nn) * 36 + kq * 4) = v;
            }
        }
        if (tid < 64) sm[F_MS + tid] = ms[(size_t)b * NTOT + n0 + tid];
        __syncthreads();

        // ---- Phase A: S for all 4 heads, 16n x 16m tile per warp ----
        float sacc[4][2][4];
        #pragma unroll
        for (int h = 0; h < 4; h++)
            #pragma unroll
            for (int j = 0; j < 2; j++)
                #pragma unroll
                for (int r = 0; r < 4; r++) sacc[h][j][r] = 0.0f;

        #pragma unroll
        for (int ks = 0; ks < 4; ks++) {
            #pragma unroll
            for (int h = 0; h < 4; h++) {
                const float* ktb = sm + F_KT + h * 2304;
                const float* qb  = sm + F_Q  + h * 2304;
                float2 aa = *(const float2*)(ktb + nA * 36 + ks * 8 + 2 * tig);
                float2 ab = *(const float2*)(ktb + (nA + 8) * 36 + ks * 8 + 2 * tig);
                #pragma unroll
                for (int j = 0; j < 2; j++) {
                    float2 bb = *(const float2*)(qb + (mA0 + j * 8 + gid) * 36 + ks * 8 + 2 * tig);
                    mma_tf32(sacc[h][j], aa, ab, bb);
                }
            }
        }

        // ---- softmax over heads, entirely in registers ----
        {
            const float msa = sm[F_MS + nA] * 0.125f;
            const float msb = sm[F_MS + nA + 8] * 0.125f;
            #pragma unroll
            for (int j = 0; j < 2; j++) {
                #pragma unroll
                for (int c = 0; c < 2; c++) {
                    int m = mA0 + j * 8 + 2 * tig + c;
                    float b0 = sm[F_BIAS + m];
                    float b1 = sm[F_BIAS + 64 + m];
                    float b2 = sm[F_BIAS + 128 + m];
                    float b3 = sm[F_BIAS + 192 + m];
                    {
                        float s0 = (sacc[0][j][c] - b0) * msa;
                        float s1 = (sacc[1][j][c] - b1) * msa;
                        float s2 = (sacc[2][j][c] - b2) * msa;
                        float s3 = (sacc[3][j][c] - b3) * msa;
                        float mx = fmaxf(fmaxf(s0, s1), fmaxf(s2, s3));
                        float e0 = __expf(s0 - mx), e1 = __expf(s1 - mx);
                        float e2 = __expf(s2 - mx), e3 = __expf(s3 - mx);
                        float inv = __fdividef(1.0f, e0 + e1 + e2 + e3);
                        sacc[0][j][c] = rn_tf32(e0 * inv);
                        sacc[1][j][c] = rn_tf32(e1 * inv);
                        sacc[2][j][c] = rn_tf32(e2 * inv);
                        sacc[3][j][c] = rn_tf32(e3 * inv);
                    }
                    {
                        float s0 = (sacc[0][j][2 + c] - b0) * msb;
                        float s1 = (sacc[1][j][2 + c] - b1) * msb;
                        float s2 = (sacc[2][j][2 + c] - b2) * msb;
                        float s3 = (sacc[3][j][2 + c] - b3) * msb;
                        float mx = fmaxf(fmaxf(s0, s1), fmaxf(s2, s3));
                        float e0 = __expf(s0 - mx), e1 = __expf(s1 - mx);
                        float e2 = __expf(s2 - mx), e3 = __expf(s3 - mx);
                        float inv = __fdividef(1.0f, e0 + e1 + e2 + e3);
                        sacc[0][j][2 + c] = rn_tf32(e0 * inv);
                        sacc[1][j][2 + c] = rn_tf32(e1 * inv);
                        sacc[2][j][2 + c] = rn_tf32(e2 * inv);
                        sacc[3][j][2 + c] = rn_tf32(e3 * inv);
                    }
                }
            }
        }

        // ---- scatter-store P[h][m][n_perm] (conflict-free banks) ----
        {
            const int pos0 = nt * 16 + ((gid & 3) << 1) + (gid >> 2);
            #pragma unroll
            for (int h = 0; h < 4; h++) {
                #pragma unroll
                for (int j = 0; j < 2; j++) {
                    float* sp = sm + F_P + h * 4352 + (mA0 + j * 8 + 2 * tig) * 68;
                    sp[pos0]          = sacc[h][j][0];
                    sp[68 + pos0]     = sacc[h][j][1];
                    sp[pos0 + 8]      = sacc[h][j][2];
                    sp[68 + pos0 + 8] = sacc[h][j][3];
                }
            }
        }
        __syncthreads();

        // ---- Phase B: O += mv * P ; mv fragments via coalesced LDG.128 ----
        #pragma unroll
        for (int ks = 0; ks < 8; ks++) {
            const float* nb = gvf + (((size_t)(n0 >> 3) + ks) << 8);
            float4 f0 = *(const float4*)(nb + lane * 4);
            float4 f1 = *(const float4*)(nb + 128 + lane * 4);
            float2 a0 = { f0.x, f0.y }, a1 = { f0.z, f0.w };
            float2 a2 = { f1.x, f1.y }, a3 = { f1.z, f1.w };
            #pragma unroll
            for (int mt = 0; mt < 8; mt++) {
                float2 bb = *(const float2*)(pb + (mt * 8 + gid) * 68 + ks * 8 + 2 * tig);
                mma_tf32(acc[0][mt], a0, a1, bb);
                mma_tf32(acc[1][mt], a2, a3, bb);
            }
        }
        __syncthreads();
    }

    // ---- writeout: fragment-direct STG.64 into g_partial ----
    {
        float* pp = g_partial +
            ((size_t)(split * BSZ + b) * CVTOT + headB * 128 + cvg * 32) * MTOT + m0;
        #pragma unroll
        for (int rt = 0; rt < 2; rt++) {
            #pragma unroll
            for (int mt = 0; mt < 8; mt++) {
                int r0 = rt * 16 + gid;
                int m  = mt * 8 + 2 * tig;
                float2 lo = { acc[rt][mt][0], acc[rt][mt][1] };
                float2 hi = { acc[rt][mt][2], acc[rt][mt][3] };
                *(float2*)(pp + (size_t)r0 * MTOT + m)       = lo;
                *(float2*)(pp + (size_t)(r0 + 8) * MTOT + m) = hi;
            }
        }
    }
}

// ---------------- assemble: reduce splits + copy qv ----------------
__global__ void assemble_kernel(const float* __restrict__ qv, float* __restrict__ out)
{
    const int total4 = BSZ * 2 * CVTOT * MTOT / 4;
    int idx = blockIdx.x * blockDim.x + threadIdx.x;
    if (idx >= total4) return;
    int gf  = idx * 4;
    int b   = gf >> 20;
    int rem = gf & ((1 << 20) - 1);
    int ch  = rem >> 10;
    int m   = rem & 1023;

    float4 r;
    if (ch < CVTOT) {
        const size_t stride = (size_t)BSZ * CVTOT * MTOT;
        size_t off = ((size_t)b * CVTOT + ch) * MTOT + m;
        float4 a0 = *reinterpret_cast<const float4*>(g_partial + 0 * stride + off);
        float4 a1 = *reinterpret_cast<const float4*>(g_partial + 1 * stride + off);
        float4 a2 = *reinterpret_cast<const float4*>(g_partial + 2 * stride + off);
        float4 a3 = *reinterpret_cast<const float4*>(g_partial + 3 * stride + off);
        r.x = a0.x + a1.x + a2.x + a3.x;
        r.y = a0.y + a1.y + a2.y + a3.y;
        r.z = a0.z + a1.z + a2.z + a3.z;
        r.w = a0.w + a1.w + a2.w + a3.w;
    } else {
        r = *reinterpret_cast<const float4*>(
                qv + ((size_t)b * CVTOT + (ch - CVTOT)) * MTOT + m);
    }
    *reinterpret_cast<float4*>(out + (size_t)gf) = r;
}

extern "C" void kernel_launch(void* const* d_in, const int* in_sizes, int n_in,
                              void* d_out, int out_size)
{
    const float* mk = (const float*)d_in[0];
    const float* qk = (const float*)d_in[1];
    const float* ms = (const float*)d_in[2];
    const float* qe = (const float*)d_in[3];
    const float* mv = (const float*)d_in[4];
    const float* qv = (const float*)d_in[5];
    float* out = (float*)d_out;

    prep_kt<<<(BSZ * 64 * NTOT + 255) / 256, 256>>>(mk);
    prep_q<<<(BSZ * HEADS_N * MTOT + 255) / 256, 256>>>(qk, qe);
    prep_mv<<<(BSZ * CVTOT * NTOT + 255) / 256, 256>>>(mv);

    cudaFuncSetAttribute(mr_main, cudaFuncAttributeMaxDynamicSharedMemorySize,
                         SM_TOTAL);
    mr_main<<<BSZ * 16 * NSPLIT, NTHREADS, SM_TOTAL>>>(ms);

    const int total4 = BSZ * 2 * CVTOT * MTOT / 4;
    assemble_kernel<<<(total4 + 255) / 256, 256>>>(qv, out);
}

// round 10
// speedup vs baseline: 1.9958x; 1.2547x over previous
#include <cuda_runtime.h>
#include <cstdint>

// ---------------- problem constants ----------------
#define HEADS_N 4
#define BSZ 2
#define NTOT 8192        // THW
#define MTOT 1024        // HW
#define CVTOT 512
#define M_T 64           // m-tile per block
#define NSPLIT 4
#define NPS (NTOT / NSPLIT)     // 2048
#define NCH 128                 // n per chunk
#define NCHUNKS (NPS / NCH)     // 16
#define NTHREADS 512

// ---------------- device scratch (no cudaMalloc allowed) ----------------
__device__ __align__(16) float g_partial[NSPLIT * BSZ * CVTOT * MTOT]; // 16 MB
// Kt fragment-native: [b][h][ngrp(n/16)][ks(4)][lane(32)][4]  (8 MB)
__device__ __align__(16) float g_ktf[BSZ * HEADS_N * (NTOT / 16) * 4 * 128];
__device__ __align__(16) float g_Q [BSZ * HEADS_N * MTOT * 32];        // [b][h][m][32k pairperm] 1 MB
__device__ __align__(16) float g_bias[BSZ * HEADS_N * MTOT];           // 32 KB
// mv fragment-native: [b][cvblk(16)][ngrp(n/8)][half(2)][lane(32)][4]  (33.5 MB)
__device__ __align__(16) float g_mvp[BSZ * CVTOT * NTOT];

// ---------------- smem layout (float offsets) ----------------
#define F_BIAS 0
#define F_MS   256                       // ms[2048] for the whole split
#define F_Q    (F_MS + 2048)             // 2304 : Q[4][64][48]
#define F_P    (F_Q + 4 * 64 * 48)       // 14592 : P[4][64][132]
#define SM_TOTAL ((F_P + 4 * 64 * 132) * 4)   // 193536 B

// ---------------- helpers ----------------
__device__ __forceinline__ float rn_tf32(float x) {
    uint32_t u;
    asm("cvt.rna.tf32.f32 %0, %1;" : "=r"(u) : "f"(x));
    return __uint_as_float(u);
}
__device__ __forceinline__ void mma_tf32(float* d, float2 aa, float2 ab, float2 bb) {
    asm volatile(
        "mma.sync.aligned.m16n8k8.row.col.f32.tf32.tf32.f32 "
        "{%0,%1,%2,%3},{%4,%5,%6,%7},{%8,%9},{%0,%1,%2,%3};"
        : "+f"(d[0]), "+f"(d[1]), "+f"(d[2]), "+f"(d[3])
        : "r"(__float_as_uint(aa.x)), "r"(__float_as_uint(ab.x)),
          "r"(__float_as_uint(aa.y)), "r"(__float_as_uint(ab.y)),
          "r"(__float_as_uint(bb.x)), "r"(__float_as_uint(bb.y)));
}

// ---------------- precompute kernels ----------------
// Kt fragment-native: value for logical (n, K): K<16 -> mk^3, K>=16 -> mk
__global__ void prep_ktf(const float* __restrict__ mk) {
    int i = blockIdx.x * blockDim.x + threadIdx.x;      // over BSZ*64*NTOT
    if (i >= BSZ * 64 * NTOT) return;
    int n  = i & (NTOT - 1);
    int ck = (i >> 13) & 63;
    int b  = i >> 19;
    float v = mk[i];
    int h = ck >> 4, c = ck & 15;
    int gid = n & 7, half = (n >> 3) & 1, ngrp = n >> 4;
    size_t blk = (((size_t)(b * HEADS_N + h) * (NTOT / 16) + ngrp)) * 4;
    #pragma unroll
    for (int t = 0; t < 2; t++) {
        int K = t ? (16 + c) : c;
        float val = t ? v : (v * v * v);
        int ks = K >> 3, r = K & 7;
        int s = ((r & 3) << 1) | (r >> 2);
        size_t off = (blk + ks) * 128 + ((gid * 4 + (s >> 1)) << 2) + half * 2 + (s & 1);
        g_ktf[off] = rn_tf32(val);
    }
}

// Q pair-ks permuted position of logical k
__device__ __host__ __forceinline__ int qpos(int K) {
    int ks = K >> 3, r = K & 7;
    int s = ((r & 3) << 1) | (r >> 2);
    return (ks >> 1) * 16 + (s >> 1) * 4 + (ks & 1) * 2 + (s & 1);
}

__global__ void prep_q(const float* __restrict__ qk, const float* __restrict__ qe) {
    int i = blockIdx.x * blockDim.x + threadIdx.x;      // over BSZ*4*MTOT
    if (i >= BSZ * HEADS_N * MTOT) return;
    int m = i & (MTOT - 1);
    int h = (i >> 10) & 3;
    int b = i >> 12;
    size_t qb = (size_t)i * 32;
    float bias = 0.0f;
    #pragma unroll
    for (int c = 0; c < 16; c++) {
        size_t gi = ((size_t)(b * 64 + h * 16 + c)) * MTOT + m;
        float e = qe[gi];
        float k = qk[gi];
        g_Q[qb + qpos(c)]      = rn_tf32(-e);
        g_Q[qb + qpos(16 + c)] = rn_tf32(2.0f * k * e);
        bias += e * k * k * k;
    }
    g_bias[i] = bias;
}

__global__ void prep_mv(const float* __restrict__ mv) {
    int i = blockIdx.x * blockDim.x + threadIdx.x;      // over BSZ*CVTOT*NTOT
    if (i >= BSZ * CVTOT * NTOT) return;
    int n   = i & (NTOT - 1);
    int row = i >> 13;            // b*512 + cv
    int b   = row >> 9;
    int cv  = row & 511;
    int blk = cv >> 5, r = cv & 31;
    int gid = r & 7, rr = r >> 3;
    int ngrp = n >> 3;
    int slot = ((n & 3) << 1) | ((n & 7) >> 2);
    int tig = slot >> 1, par = slot & 1;
    size_t off = (((size_t)(b * 16 + blk) * (NTOT / 8) + ngrp) << 8)
               + ((size_t)(rr >> 1) << 7) + ((gid * 4 + tig) << 2)
               + ((rr & 1) << 1) + par;
    g_mvp[off] = rn_tf32(mv[i]);
}

// ---------------- main fused kernel ----------------
__global__ void __launch_bounds__(NTHREADS, 1)
mr_main(const float* __restrict__ ms)
{
    extern __shared__ float sm[];
    const int tid  = threadIdx.x;
    const int w    = tid >> 5;
    const int lane = tid & 31;
    const int gid  = lane >> 2;      // 0..7
    const int tig  = lane & 3;       // 0..3

    const int bx    = blockIdx.x;    // 128 blocks
    const int split = bx & 3;
    const int mtile = (bx >> 2) & 15;
    const int b     = bx >> 6;
    const int m0    = mtile * M_T;
    const int nbase = split * NPS;

    // ---- stage bias + ms (whole split) + Q (block-constant) ----
    if (tid < 256)
        sm[F_BIAS + tid] = g_bias[(size_t)(b * HEADS_N + (tid >> 6)) * MTOT + m0 + (tid & 63)];
    #pragma unroll
    for (int it = 0; it < 4; it++) {
        int i = tid + it * NTHREADS;
        sm[F_MS + i] = ms[(size_t)b * NTOT + nbase + i];
    }
    {
        const float4* src = (const float4*)(g_Q + (size_t)(b * HEADS_N) * MTOT * 32);
        #pragma unroll
        for (int it = 0; it < 4; it++) {
            int j = tid + it * NTHREADS;         // 2048 float4
            int kq = j & 7, mm = (j >> 3) & 63, h = j >> 9;
            float4 v = src[((size_t)h * MTOT + m0 + mm) * 8 + kq];
            *(float4*)(sm + F_Q + (h * 64 + mm) * 48 + kq * 4) = v;
        }
    }

    // Phase A mapping: warp = (ntile, mtile4), all 4 heads in-register
    const int nt  = w & 3;
    const int mA0 = (w >> 2) * 16;
    // Phase B mapping: one head per warp, cv32 x m64
    const int headB = w >> 2;
    const int cvg   = w & 3;

    float acc[2][8][4];   // O accumulators [cvtile][mt][reg]
    #pragma unroll
    for (int rt = 0; rt < 2; rt++)
        #pragma unroll
        for (int mt = 0; mt < 8; mt++)
            #pragma unroll
            for (int r = 0; r < 4; r++) acc[rt][mt][r] = 0.0f;

    // fragment-native bases
    const float* gvf = g_mvp +
        (((size_t)(b * 16 + headB * 4 + cvg)) * (NTOT / 8)) * 256;
    const float* ktb0 = g_ktf + ((size_t)(b * HEADS_N) * (NTOT / 16)) * 512;
    const float* pb = sm + F_P + headB * 8448;   // 64*132

    __syncthreads();

    for (int chunk = 0; chunk < NCHUNKS; chunk++) {
        const int n0 = nbase + chunk * NCH;

        // ===== Phase A: two 64-n sub-passes =====
        #pragma unroll
        for (int p = 0; p < 2; p++) {
            float sacc[4][2][4];
            #pragma unroll
            for (int h = 0; h < 4; h++)
                #pragma unroll
                for (int j = 0; j < 2; j++)
                    #pragma unroll
                    for (int r = 0; r < 4; r++) sacc[h][j][r] = 0.0f;

            const int ngrp = (n0 >> 4) + p * 4 + nt;
            #pragma unroll
            for (int kp = 0; kp < 2; kp++) {
                #pragma unroll
                for (int h = 0; h < 4; h++) {
                    const float* kb = ktb0 +
                        (((size_t)h * (NTOT / 16) + ngrp) * 4 + 2 * kp) * 128 + lane * 4;
                    float4 fA0 = *(const float4*)(kb);
                    float4 fA1 = *(const float4*)(kb + 128);
                    const float* qb = sm + F_Q + h * 3072 + kp * 16 + tig * 4;
                    #pragma unroll
                    for (int j = 0; j < 2; j++) {
                        float4 bq = *(const float4*)(qb + (mA0 + j * 8 + gid) * 48);
                        mma_tf32(sacc[h][j], make_float2(fA0.x, fA0.y),
                                 make_float2(fA0.z, fA0.w), make_float2(bq.x, bq.y));
                        mma_tf32(sacc[h][j], make_float2(fA1.x, fA1.y),
                                 make_float2(fA1.z, fA1.w), make_float2(bq.z, bq.w));
                    }
                }
            }

            // ---- softmax over heads, in registers ----
            {
                const int nAl = p * 64 + nt * 16 + gid;
                const float msa = sm[F_MS + chunk * NCH + nAl] * 0.125f;
                const float msb = sm[F_MS + chunk * NCH + nAl + 8] * 0.125f;
                #pragma unroll
                for (int j = 0; j < 2; j++) {
                    #pragma unroll
                    for (int c = 0; c < 2; c++) {
                        int m = mA0 + j * 8 + 2 * tig + c;
                        float b0 = sm[F_BIAS + m];
                        float b1 = sm[F_BIAS + 64 + m];
                        float b2 = sm[F_BIAS + 128 + m];
                        float b3 = sm[F_BIAS + 192 + m];
                        {
                            float s0 = (sacc[0][j][c] - b0) * msa;
                            float s1 = (sacc[1][j][c] - b1) * msa;
                            float s2 = (sacc[2][j][c] - b2) * msa;
                            float s3 = (sacc[3][j][c] - b3) * msa;
                            float mx = fmaxf(fmaxf(s0, s1), fmaxf(s2, s3));
                            float e0 = __expf(s0 - mx), e1 = __expf(s1 - mx);
                            float e2 = __expf(s2 - mx), e3 = __expf(s3 - mx);
                            float inv = __fdividef(1.0f, e0 + e1 + e2 + e3);
                            sacc[0][j][c] = rn_tf32(e0 * inv);
                            sacc[1][j][c] = rn_tf32(e1 * inv);
                            sacc[2][j][c] = rn_tf32(e2 * inv);
                            sacc[3][j][c] = rn_tf32(e3 * inv);
                        }
                        {
                            float s0 = (sacc[0][j][2 + c] - b0) * msb;
                            float s1 = (sacc[1][j][2 + c] - b1) * msb;
                            float s2 = (sacc[2][j][2 + c] - b2) * msb;
                            float s3 = (sacc[3][j][2 + c] - b3) * msb;
                            float mx = fmaxf(fmaxf(s0, s1), fmaxf(s2, s3));
                            float e0 = __expf(s0 - mx), e1 = __expf(s1 - mx);
                            float e2 = __expf(s2 - mx), e3 = __expf(s3 - mx);
                            float inv = __fdividef(1.0f, e0 + e1 + e2 + e3);
                            sacc[0][j][2 + c] = rn_tf32(e0 * inv);
                            sacc[1][j][2 + c] = rn_tf32(e1 * inv);
                            sacc[2][j][2 + c] = rn_tf32(e2 * inv);
                            sacc[3][j][2 + c] = rn_tf32(e3 * inv);
                        }
                    }
                }
            }

            // ---- scatter-store P[h][m][npos] ----
            {
                const int pos0 = p * 64 + nt * 16 + ((gid & 3) << 1) + (gid >> 2);
                #pragma unroll
                for (int h = 0; h < 4; h++) {
                    #pragma unroll
                    for (int j = 0; j < 2; j++) {
                        float* sp = sm + F_P + h * 8448 + (mA0 + j * 8 + 2 * tig) * 132;
                        sp[pos0]           = sacc[h][j][0];
                        sp[132 + pos0]     = sacc[h][j][1];
                        sp[pos0 + 8]       = sacc[h][j][2];
                        sp[132 + pos0 + 8] = sacc[h][j][3];
                    }
                }
            }
        }
        __syncthreads();

        // ===== Phase B: O += mv * P over 128 n =====
        #pragma unroll
        for (int ks = 0; ks < 16; ks++) {
            const float* nb = gvf + (((size_t)(n0 >> 3) + ks) << 8);
            float4 f0 = *(const float4*)(nb + lane * 4);
            float4 f1 = *(const float4*)(nb + 128 + lane * 4);
            float2 a0 = { f0.x, f0.y }, a1 = { f0.z, f0.w };
            float2 a2 = { f1.x, f1.y }, a3 = { f1.z, f1.w };
            #pragma unroll
            for (int mt = 0; mt < 8; mt++) {
                float2 bb = *(const float2*)(pb + (mt * 8 + gid) * 132 + ks * 8 + 2 * tig);
                mma_tf32(acc[0][mt], a0, a1, bb);
                mma_tf32(acc[1][mt], a2, a3, bb);
            }
        }
        __syncthreads();
    }

    // ---- writeout: fragment-direct STG.64 into g_partial ----
    {
        float* pp = g_partial +
            ((size_t)(split * BSZ + b) * CVTOT + headB * 128 + cvg * 32) * MTOT + m0;
        #pragma unroll
        for (int rt = 0; rt < 2; rt++) {
            #pragma unroll
            for (int mt = 0; mt < 8; mt++) {
                int r0 = rt * 16 + gid;
                int m  = mt * 8 + 2 * tig;
                float2 lo = { acc[rt][mt][0], acc[rt][mt][1] };
                float2 hi = { acc[rt][mt][2], acc[rt][mt][3] };
                *(float2*)(pp + (size_t)r0 * MTOT + m)       = lo;
                *(float2*)(pp + (size_t)(r0 + 8) * MTOT + m) = hi;
            }
        }
    }
}

// ---------------- assemble: reduce splits + copy qv ----------------
__global__ void assemble_kernel(const float* __restrict__ qv, float* __restrict__ out)
{
    const int total4 = BSZ * 2 * CVTOT * MTOT / 4;
    int idx = blockIdx.x * blockDim.x + threadIdx.x;
    if (idx >= total4) return;
    int gf  = idx * 4;
    int b   = gf >> 20;
    int rem = gf & ((1 << 20) - 1);
    int ch  = rem >> 10;
    int m   = rem & 1023;

    float4 r;
    if (ch < CVTOT) {
        const size_t stride = (size_t)BSZ * CVTOT * MTOT;
        size_t off = ((size_t)b * CVTOT + ch) * MTOT + m;
        float4 a0 = *reinterpret_cast<const float4*>(g_partial + 0 * stride + off);
        float4 a1 = *reinterpret_cast<const float4*>(g_partial + 1 * stride + off);
        float4 a2 = *reinterpret_cast<const float4*>(g_partial + 2 * stride + off);
        float4 a3 = *reinterpret_cast<const float4*>(g_partial + 3 * stride + off);
        r.x = a0.x + a1.x + a2.x + a3.x;
        r.y = a0.y + a1.y + a2.y + a3.y;
        r.z = a0.z + a1.z + a2.z + a3.z;
        r.w = a0.w + a1.w + a2.w + a3.w;
    } else {
        r = *reinterpret_cast<const float4*>(
                qv + ((size_t)b * CVTOT + (ch - CVTOT)) * MTOT + m);
    }
    *reinterpret_cast<float4*>(out + (size_t)gf) = r;
}

extern "C" void kernel_launch(void* const* d_in, const int* in_sizes, int n_in,
                              void* d_out, int out_size)
{
    const float* mk = (const float*)d_in[0];
    const float* qk = (const float*)d_in[1];
    const float* ms = (const float*)d_in[2];
    const float* qe = (const float*)d_in[3];
    const float* mv = (const float*)d_in[4];
    const float* qv = (const float*)d_in[5];
    float* out = (float*)d_out;

    prep_ktf<<<(BSZ * 64 * NTOT + 255) / 256, 256>>>(mk);
    prep_q<<<(BSZ * HEADS_N * MTOT + 255) / 256, 256>>>(qk, qe);
    prep_mv<<<(BSZ * CVTOT * NTOT + 255) / 256, 256>>>(mv);

    cudaFuncSetAttribute(mr_main, cudaFuncAttributeMaxDynamicSharedMemorySize,
                         SM_TOTAL);
    mr_main<<<BSZ * 16 * NSPLIT, NTHREADS, SM_TOTAL>>>(ms);

    const int total4 = BSZ * 2 * CVTOT * MTOT / 4;
    assemble_kernel<<<(total4 + 255) / 256, 256>>>(qv, out);
}

// round 11
// speedup vs baseline: 2.0910x; 1.0477x over previous
#include <cuda_runtime.h>
#include <cstdint>

// ---------------- problem constants ----------------
#define HEADS_N 4
#define BSZ 2
#define NTOT 8192        // THW
#define MTOT 1024        // HW
#define CVTOT 512
#define M_T 64           // m-tile per block
#define NSPLIT 4
#define NPS (NTOT / NSPLIT)     // 2048
#define NCH 128                 // n per chunk
#define NCHUNKS (NPS / NCH)     // 16
#define NTHREADS 512
#define PSTR 136                // P row stride (== 8 mod 32 -> conflict-free LDS.64)

// ---------------- device scratch (no cudaMalloc allowed) ----------------
__device__ __align__(16) float g_partial[NSPLIT * BSZ * CVTOT * MTOT]; // 16 MB
// Kt fragment-native: [b][h][ngrp(n/16)][ks(4)][lane(32)][4]  (8 MB)
__device__ __align__(16) float g_ktf[BSZ * HEADS_N * (NTOT / 16) * 4 * 128];
__device__ __align__(16) float g_Q [BSZ * HEADS_N * MTOT * 32];        // [b][h][m][32k pairperm] 1 MB
__device__ __align__(16) float g_bias[BSZ * HEADS_N * MTOT];           // 32 KB
// mv fragment-native: [b][cvblk(16)][ngrp(n/8)][half(2)][lane(32)][4]  (33.5 MB)
__device__ __align__(16) float g_mvp[BSZ * CVTOT * NTOT];

// ---------------- smem layout (float offsets) ----------------
#define F_BIAS 0
#define F_MS   256                       // ms[2048] for the whole split
#define F_Q    (F_MS + 2048)             // 2304 : Q[4][64][48]
#define F_P    (F_Q + 4 * 64 * 48)       // 14592 : P[4][64][PSTR]
#define SM_TOTAL ((F_P + 4 * 64 * PSTR) * 4)   // 197632 B

// ---------------- helpers ----------------
__device__ __forceinline__ float rn_tf32(float x) {
    uint32_t u;
    asm("cvt.rna.tf32.f32 %0, %1;" : "=r"(u) : "f"(x));
    return __uint_as_float(u);
}
__device__ __forceinline__ float ex2f(float x) {
    float y;
    asm("ex2.approx.f32 %0, %1;" : "=f"(y) : "f"(x));
    return y;
}
__device__ __forceinline__ void mma_tf32(float* d, float2 aa, float2 ab, float2 bb) {
    asm volatile(
        "mma.sync.aligned.m16n8k8.row.col.f32.tf32.tf32.f32 "
        "{%0,%1,%2,%3},{%4,%5,%6,%7},{%8,%9},{%0,%1,%2,%3};"
        : "+f"(d[0]), "+f"(d[1]), "+f"(d[2]), "+f"(d[3])
        : "r"(__float_as_uint(aa.x)), "r"(__float_as_uint(ab.x)),
          "r"(__float_as_uint(aa.y)), "r"(__float_as_uint(ab.y)),
          "r"(__float_as_uint(bb.x)), "r"(__float_as_uint(bb.y)));
}

// ---------------- precompute kernels ----------------
// Kt fragment-native: value for logical (n, K): K<16 -> mk^3, K>=16 -> mk
__global__ void prep_ktf(const float* __restrict__ mk) {
    int i = blockIdx.x * blockDim.x + threadIdx.x;      // over BSZ*64*NTOT
    if (i >= BSZ * 64 * NTOT) return;
    int n  = i & (NTOT - 1);
    int ck = (i >> 13) & 63;
    int b  = i >> 19;
    float v = mk[i];
    int h = ck >> 4, c = ck & 15;
    int gid = n & 7, half = (n >> 3) & 1, ngrp = n >> 4;
    size_t blk = (((size_t)(b * HEADS_N + h) * (NTOT / 16) + ngrp)) * 4;
    #pragma unroll
    for (int t = 0; t < 2; t++) {
        int K = t ? (16 + c) : c;
        float val = t ? v : (v * v * v);
        int ks = K >> 3, r = K & 7;
        int s = ((r & 3) << 1) | (r >> 2);
        size_t off = (blk + ks) * 128 + ((gid * 4 + (s >> 1)) << 2) + half * 2 + (s & 1);
        g_ktf[off] = rn_tf32(val);
    }
}

// Q pair-ks permuted position of logical k
__device__ __host__ __forceinline__ int qpos(int K) {
    int ks = K >> 3, r = K & 7;
    int s = ((r & 3) << 1) | (r >> 2);
    return (ks >> 1) * 16 + (s >> 1) * 4 + (ks & 1) * 2 + (s & 1);
}

__global__ void prep_q(const float* __restrict__ qk, const float* __restrict__ qe) {
    int i = blockIdx.x * blockDim.x + threadIdx.x;      // over BSZ*4*MTOT
    if (i >= BSZ * HEADS_N * MTOT) return;
    int m = i & (MTOT - 1);
    int h = (i >> 10) & 3;
    int b = i >> 12;
    size_t qb = (size_t)i * 32;
    float bias = 0.0f;
    #pragma unroll
    for (int c = 0; c < 16; c++) {
        size_t gi = ((size_t)(b * 64 + h * 16 + c)) * MTOT + m;
        float e = qe[gi];
        float k = qk[gi];
        g_Q[qb + qpos(c)]      = rn_tf32(-e);
        g_Q[qb + qpos(16 + c)] = rn_tf32(2.0f * k * e);
        bias += e * k * k * k;
    }
    g_bias[i] = bias;
}

// gather-style: one thread -> one output float4 (coalesced STG.128)
__global__ void prep_mv(const float* __restrict__ mv) {
    int f = blockIdx.x * blockDim.x + threadIdx.x;   // float4 index
    if (f >= BSZ * CVTOT * NTOT / 4) return;
    int tig  = f & 3;
    int gid  = (f >> 2) & 7;
    int half = (f >> 5) & 1;
    int ngrp = (f >> 6) & (NTOT / 8 - 1);
    int blk  = (f >> 16) & 15;
    int b    = f >> 20;
    int n0  = ngrp * 8 + tig;
    int cvb = blk * 32 + half * 16 + gid;
    const float* src = mv + ((size_t)(b * CVTOT) << 13);
    float4 v;
    v.x = rn_tf32(src[((size_t)cvb << 13) + n0]);
    v.y = rn_tf32(src[((size_t)cvb << 13) + n0 + 4]);
    v.z = rn_tf32(src[((size_t)(cvb + 8) << 13) + n0]);
    v.w = rn_tf32(src[((size_t)(cvb + 8) << 13) + n0 + 4]);
    *(float4*)(g_mvp + ((size_t)f << 2)) = v;
}

// ---------------- main fused kernel ----------------
__global__ void __launch_bounds__(NTHREADS, 1)
mr_main(const float* __restrict__ ms)
{
    extern __shared__ float sm[];
    const int tid  = threadIdx.x;
    const int w    = tid >> 5;
    const int lane = tid & 31;
    const int gid  = lane >> 2;      // 0..7
    const int tig  = lane & 3;       // 0..3

    const int bx    = blockIdx.x;    // 128 blocks
    const int split = bx & 3;
    const int mtile = (bx >> 2) & 15;
    const int b     = bx >> 6;
    const int m0    = mtile * M_T;
    const int nbase = split * NPS;

    // ---- stage bias + ms (whole split) + Q (block-constant) ----
    if (tid < 256)
        sm[F_BIAS + tid] = g_bias[(size_t)(b * HEADS_N + (tid >> 6)) * MTOT + m0 + (tid & 63)];
    #pragma unroll
    for (int it = 0; it < 4; it++) {
        int i = tid + it * NTHREADS;
        sm[F_MS + i] = ms[(size_t)b * NTOT + nbase + i];
    }
    {
        const float4* src = (const float4*)(g_Q + (size_t)(b * HEADS_N) * MTOT * 32);
        #pragma unroll
        for (int it = 0; it < 4; it++) {
            int j = tid + it * NTHREADS;         // 2048 float4
            int kq = j & 7, mm = (j >> 3) & 63, h = j >> 9;
            float4 v = src[((size_t)h * MTOT + m0 + mm) * 8 + kq];
            *(float4*)(sm + F_Q + (h * 64 + mm) * 48 + kq * 4) = v;
        }
    }

    // Phase A mapping: warp = (ntile, mtile4), all 4 heads in-register
    const int nt  = w & 3;
    const int mA0 = (w >> 2) * 16;
    // Phase B mapping: one head per warp, cv32 x m64
    const int headB = w >> 2;
    const int cvg   = w & 3;

    float acc[2][8][4];   // O accumulators [cvtile][mt][reg]
    #pragma unroll
    for (int rt = 0; rt < 2; rt++)
        #pragma unroll
        for (int mt = 0; mt < 8; mt++)
            #pragma unroll
            for (int r = 0; r < 4; r++) acc[rt][mt][r] = 0.0f;

    // fragment-native bases
    const float* gvf = g_mvp +
        (((size_t)(b * 16 + headB * 4 + cvg)) * (NTOT / 8)) * 256;
    const float* ktb0 = g_ktf + ((size_t)(b * HEADS_N) * (NTOT / 16)) * 512;
    const float* pb = sm + F_P + headB * (64 * PSTR);

    const float SC = 0.18033688f;   // 0.125 * log2(e)

    __syncthreads();

    for (int chunk = 0; chunk < NCHUNKS; chunk++) {
        const int n0 = nbase + chunk * NCH;

        // ===== Phase A: two 64-n sub-passes =====
        #pragma unroll
        for (int p = 0; p < 2; p++) {
            float sacc[4][2][4];
            #pragma unroll
            for (int h = 0; h < 4; h++)
                #pragma unroll
                for (int j = 0; j < 2; j++)
                    #pragma unroll
                    for (int r = 0; r < 4; r++) sacc[h][j][r] = 0.0f;

            const int ngrp = (n0 >> 4) + p * 4 + nt;
            #pragma unroll
            for (int kp = 0; kp < 2; kp++) {
                #pragma unroll
                for (int h = 0; h < 4; h++) {
                    const float* kb = ktb0 +
                        (((size_t)h * (NTOT / 16) + ngrp) * 4 + 2 * kp) * 128 + lane * 4;
                    float4 fA0 = *(const float4*)(kb);
                    float4 fA1 = *(const float4*)(kb + 128);
                    const float* qb = sm + F_Q + h * 3072 + kp * 16 + tig * 4;
                    #pragma unroll
                    for (int j = 0; j < 2; j++) {
                        float4 bq = *(const float4*)(qb + (mA0 + j * 8 + gid) * 48);
                        mma_tf32(sacc[h][j], make_float2(fA0.x, fA0.y),
                                 make_float2(fA0.z, fA0.w), make_float2(bq.x, bq.y));
                        mma_tf32(sacc[h][j], make_float2(fA1.x, fA1.y),
                                 make_float2(fA1.z, fA1.w), make_float2(bq.z, bq.w));
                    }
                }
            }

            // ---- softmax over heads, in registers (log2 domain) ----
            {
                const int nAl = p * 64 + nt * 16 + gid;
                const float msa = sm[F_MS + chunk * NCH + nAl] * SC;
                const float msb = sm[F_MS + chunk * NCH + nAl + 8] * SC;
                #pragma unroll
                for (int j = 0; j < 2; j++) {
                    #pragma unroll
                    for (int c = 0; c < 2; c++) {
                        int m = mA0 + j * 8 + 2 * tig + c;
                        float b0 = sm[F_BIAS + m];
                        float b1 = sm[F_BIAS + 64 + m];
                        float b2 = sm[F_BIAS + 128 + m];
                        float b3 = sm[F_BIAS + 192 + m];
                        {
                            float s0 = (sacc[0][j][c] - b0) * msa;
                            float s1 = (sacc[1][j][c] - b1) * msa;
                            float s2 = (sacc[2][j][c] - b2) * msa;
                            float s3 = (sacc[3][j][c] - b3) * msa;
                            float mx = fmaxf(fmaxf(s0, s1), fmaxf(s2, s3));
                            float e0 = ex2f(s0 - mx), e1 = ex2f(s1 - mx);
                            float e2 = ex2f(s2 - mx), e3 = ex2f(s3 - mx);
                            float inv = __fdividef(1.0f, e0 + e1 + e2 + e3);
                            sacc[0][j][c] = rn_tf32(e0 * inv);
                            sacc[1][j][c] = rn_tf32(e1 * inv);
                            sacc[2][j][c] = rn_tf32(e2 * inv);
                            sacc[3][j][c] = rn_tf32(e3 * inv);
                        }
                        {
                            float s0 = (sacc[0][j][2 + c] - b0) * msb;
                            float s1 = (sacc[1][j][2 + c] - b1) * msb;
                            float s2 = (sacc[2][j][2 + c] - b2) * msb;
                            float s3 = (sacc[3][j][2 + c] - b3) * msb;
                            float mx = fmaxf(fmaxf(s0, s1), fmaxf(s2, s3));
                            float e0 = ex2f(s0 - mx), e1 = ex2f(s1 - mx);
                            float e2 = ex2f(s2 - mx), e3 = ex2f(s3 - mx);
                            float inv = __fdividef(1.0f, e0 + e1 + e2 + e3);
                            sacc[0][j][2 + c] = rn_tf32(e0 * inv);
                            sacc[1][j][2 + c] = rn_tf32(e1 * inv);
                            sacc[2][j][2 + c] = rn_tf32(e2 * inv);
                            sacc[3][j][2 + c] = rn_tf32(e3 * inv);
                        }
                    }
                }
            }

            // ---- scatter-store P[h][m][npos] ----
            {
                const int pos0 = p * 64 + nt * 16 + ((gid & 3) << 1) + (gid >> 2);
                #pragma unroll
                for (int h = 0; h < 4; h++) {
                    #pragma unroll
                    for (int j = 0; j < 2; j++) {
                        float* sp = sm + F_P + h * (64 * PSTR) + (mA0 + j * 8 + 2 * tig) * PSTR;
                        sp[pos0]            = sacc[h][j][0];
                        sp[PSTR + pos0]     = sacc[h][j][1];
                        sp[pos0 + 8]        = sacc[h][j][2];
                        sp[PSTR + pos0 + 8] = sacc[h][j][3];
                    }
                }
            }
        }
        __syncthreads();

        // ===== Phase B: O += mv * P over 128 n =====
        #pragma unroll
        for (int ks = 0; ks < 16; ks++) {
            const float* nb = gvf + (((size_t)(n0 >> 3) + ks) << 8);
            float4 f0 = *(const float4*)(nb + lane * 4);
            float4 f1 = *(const float4*)(nb + 128 + lane * 4);
            float2 a0 = { f0.x, f0.y }, a1 = { f0.z, f0.w };
            float2 a2 = { f1.x, f1.y }, a3 = { f1.z, f1.w };
            #pragma unroll
            for (int mt = 0; mt < 8; mt++) {
                float2 bb = *(const float2*)(pb + (mt * 8 + gid) * PSTR + ks * 8 + 2 * tig);
                mma_tf32(acc[0][mt], a0, a1, bb);
                mma_tf32(acc[1][mt], a2, a3, bb);
            }
        }
        __syncthreads();
    }

    // ---- writeout: fragment-direct STG.64 into g_partial ----
    {
        float* pp = g_partial +
            ((size_t)(split * BSZ + b) * CVTOT + headB * 128 + cvg * 32) * MTOT + m0;
        #pragma unroll
        for (int rt = 0; rt < 2; rt++) {
            #pragma unroll
            for (int mt = 0; mt < 8; mt++) {
                int r0 = rt * 16 + gid;
                int m  = mt * 8 + 2 * tig;
                float2 lo = { acc[rt][mt][0], acc[rt][mt][1] };
                float2 hi = { acc[rt][mt][2], acc[rt][mt][3] };
                *(float2*)(pp + (size_t)r0 * MTOT + m)       = lo;
                *(float2*)(pp + (size_t)(r0 + 8) * MTOT + m) = hi;
            }
        }
    }
}

// ---------------- assemble: reduce splits + copy qv ----------------
__global__ void assemble_kernel(const float* __restrict__ qv, float* __restrict__ out)
{
    const int total4 = BSZ * 2 * CVTOT * MTOT / 4;
    int idx = blockIdx.x * blockDim.x + threadIdx.x;
    if (idx >= total4) return;
    int gf  = idx * 4;
    int b   = gf >> 20;
    int rem = gf & ((1 << 20) - 1);
    int ch  = rem >> 10;
    int m   = rem & 1023;

    float4 r;
    if (ch < CVTOT) {
        const size_t stride = (size_t)BSZ * CVTOT * MTOT;
        size_t off = ((size_t)b * CVTOT + ch) * MTOT + m;
        float4 a0 = *reinterpret_cast<const float4*>(g_partial + 0 * stride + off);
        float4 a1 = *reinterpret_cast<const float4*>(g_partial + 1 * stride + off);
        float4 a2 = *reinterpret_cast<const float4*>(g_partial + 2 * stride + off);
        float4 a3 = *reinterpret_cast<const float4*>(g_partial + 3 * stride + off);
        r.x = a0.x + a1.x + a2.x + a3.x;
        r.y = a0.y + a1.y + a2.y + a3.y;
        r.z = a0.z + a1.z + a2.z + a3.z;
        r.w = a0.w + a1.w + a2.w + a3.w;
    } else {
        r = *reinterpret_cast<const float4*>(
                qv + ((size_t)b * CVTOT + (ch - CVTOT)) * MTOT + m);
    }
    *reinterpret_cast<float4*>(out + (size_t)gf) = r;
}

extern "C" void kernel_launch(void* const* d_in, const int* in_sizes, int n_in,
                              void* d_out, int out_size)
{
    const float* mk = (const float*)d_in[0];
    const float* qk = (const float*)d_in[1];
    const float* ms = (const float*)d_in[2];
    const float* qe = (const float*)d_in[3];
    const float* mv = (const float*)d_in[4];
    const float* qv = (const float*)d_in[5];
    float* out = (float*)d_out;

    prep_ktf<<<(BSZ * 64 * NTOT + 255) / 256, 256>>>(mk);
    prep_q<<<(BSZ * HEADS_N * MTOT + 255) / 256, 256>>>(qk, qe);
    prep_mv<<<(BSZ * CVTOT * NTOT / 4 + 255) / 256, 256>>>(mv);

    cudaFuncSetAttribute(mr_main, cudaFuncAttributeMaxDynamicSharedMemorySize,
                         SM_TOTAL);
    mr_main<<<BSZ * 16 * NSPLIT, NTHREADS, SM_TOTAL>>>(ms);

    const int total4 = BSZ * 2 * CVTOT * MTOT / 4;
    assemble_kernel<<<(total4 + 255) / 256, 256>>>(qv, out);
}